// round 17
// baseline (speedup 1.0000x reference)
#include <cuda_runtime.h>
#include <cuda_bf16.h>
#include <math.h>
#include <stdint.h>

// ---------------- problem constants ----------------
#define Bb   2
#define Ss   1024
#define Dd   2048
#define Hh   16
#define DHh  128
#define Ee   8
#define HIDh 4096
#define Tt   (Bb * Ss)       // 2048 tokens
#define NPAIR (Tt * 2)       // 4096 (token, expert) pairs
#define QKVN (3 * Dd)        // 6144
#define GUN  (2 * HIDh)      // 8192

// ---------------- device scratch ----------------
// fp32
__device__ float g_qkv[(size_t)Tt * QKVN];
__device__ float g_x2 [Tt * Dd];
__device__ float g_xn2[Tt * Dd];
__device__ float g_eo [(size_t)NPAIR * Dd];
__device__ float g_bqkv[QKVN];
// bf16 hi/lo planes (x = hi + lo split)
__device__ __nv_bfloat16 g_hxn1[Tt * Dd], g_lxn1[Tt * Dd];
__device__ __nv_bfloat16 g_hatt[Tt * Dd], g_latt[Tt * Dd];
__device__ __nv_bfloat16 g_hxn2[Tt * Dd], g_lxn2[Tt * Dd];
__device__ __nv_bfloat16 g_hgb [(size_t)NPAIR * HIDh], g_lgb[(size_t)NPAIR * HIDh];
__device__ __nv_bfloat16 g_hwqkv[(size_t)QKVN * Dd], g_lwqkv[(size_t)QKVN * Dd];
__device__ __nv_bfloat16 g_hwo [Dd * Dd], g_lwo[Dd * Dd];
// routing
__device__ int   g_tid2[NPAIR];
__device__ float g_twt [NPAIR];
__device__ int   g_cnt[Ee];
__device__ int   g_off[Ee];
__device__ int   g_tok[NPAIR];
__device__ int   g_prow[NPAIR];

// ---------------- helpers ----------------
__device__ __forceinline__ uint32_t smem_u32(const void* p) {
    uint32_t a;
    asm("{ .reg .u64 t; cvta.to.shared.u64 t, %1; cvt.u32.u64 %0, t; }" : "=r"(a) : "l"(p));
    return a;
}
__device__ __forceinline__ uint32_t swz128(uint32_t off) {
    return off ^ ((off >> 3) & 0x70);
}
__device__ __forceinline__ void ldsm_x4(uint32_t* r, uint32_t addr) {
    asm volatile("ldmatrix.sync.aligned.m8n8.x4.shared.b16 {%0,%1,%2,%3}, [%4];"
                 : "=r"(r[0]), "=r"(r[1]), "=r"(r[2]), "=r"(r[3]) : "r"(addr));
}
__device__ __forceinline__ void mma_bf16(float* c, const uint32_t* a, uint32_t b0, uint32_t b1) {
    asm volatile("mma.sync.aligned.m16n8k16.row.col.f32.bf16.bf16.f32 "
                 "{%0,%1,%2,%3}, {%4,%5,%6,%7}, {%8,%9}, {%0,%1,%2,%3};"
                 : "+f"(c[0]), "+f"(c[1]), "+f"(c[2]), "+f"(c[3])
                 : "r"(a[0]), "r"(a[1]), "r"(a[2]), "r"(a[3]), "r"(b0), "r"(b1));
}
__device__ __forceinline__ void cpa16(uint32_t dst, const void* src) {
    asm volatile("cp.async.cg.shared.global [%0], [%1], 16;" :: "r"(dst), "l"(src) : "memory");
}
__device__ __forceinline__ void split2(float f, __nv_bfloat16& h, __nv_bfloat16& l) {
    h = __float2bfloat16(f);
    l = __float2bfloat16(f - __bfloat162float(h));
}
__device__ __forceinline__ void store_split4(__nv_bfloat16* oh, __nv_bfloat16* ol,
                                             size_t o, float4 v) {
    __nv_bfloat16 h[4], l[4];
    split2(v.x, h[0], l[0]); split2(v.y, h[1], l[1]);
    split2(v.z, h[2], l[2]); split2(v.w, h[3], l[3]);
    *(ushort4*)(oh + o) = make_ushort4(*(uint16_t*)&h[0], *(uint16_t*)&h[1],
                                       *(uint16_t*)&h[2], *(uint16_t*)&h[3]);
    *(ushort4*)(ol + o) = make_ushort4(*(uint16_t*)&l[0], *(uint16_t*)&l[1],
                                       *(uint16_t*)&l[2], *(uint16_t*)&l[3]);
}

// ---------------- pack conversion (dense weights only), MLP=4 ----------------
__global__ void pack_kernel(const float* __restrict__ in,
                            __nv_bfloat16* __restrict__ oh,
                            __nv_bfloat16* __restrict__ ol, size_t nf4q) {
    size_t t = (size_t)blockIdx.x * 256 + threadIdx.x;
    float4 v[4];
    #pragma unroll
    for (int q = 0; q < 4; q++) v[q] = ((const float4*)in)[t + q * nf4q];
    #pragma unroll
    for (int q = 0; q < 4; q++) store_split4(oh, ol, (t + q * nf4q) * 4, v[q]);
}

__global__ void bias_cat_kernel(const float* __restrict__ bq, const float* __restrict__ bk,
                                const float* __restrict__ bv) {
    int i = blockIdx.x * 256 + threadIdx.x;
    float v = (i < Dd) ? bq[i] : (i < 2 * Dd) ? bk[i - Dd] : bv[i - 2 * Dd];
    g_bqkv[i] = v;
}

// ---------------- 3x-bf16 mma.sync GEMM, 3-stage cp.async pipeline ----------------
// C[M,N] = A[M,K] @ B[N,K]^T. CTA tile 128x128, K-tile 32 elems.
// Smem row (128B, swz128): [0,64) hi bf16 k0..31, [64,128) lo bf16 k0..31.
// SILU: N-cols are interleaved (gate,up) pairs; epilogue writes silu planes.
// CONVB: B comes from fp32 gmem (Bf0/Bf1), split to hi/lo in the loader.
// ROPE: apply head-indexed rotation to q/k column regions in the epilogue.
#define STAGE_B  32768
#define TC_SMEM  (1024 + 3 * STAGE_B)

template <bool EXPERT, bool GATHER, bool SILU, bool CONVB, bool ROPE>
__global__ __launch_bounds__(256, 2)
void tc_gemm(const __nv_bfloat16* __restrict__ Ahi, const __nv_bfloat16* __restrict__ Alo,
             const __nv_bfloat16* __restrict__ Bhi, const __nv_bfloat16* __restrict__ Blo,
             const float* __restrict__ Bf0, const float* __restrict__ Bf1,
             float* __restrict__ C, const float* __restrict__ bias,
             const float* __restrict__ resid, int N, int K) {
    extern __shared__ float sm[];
    const int tid = threadIdx.x;

    int bm, bn, cnt = 0, seg = 0, e = 0;
    if (EXPERT) {
        e = blockIdx.z; cnt = g_cnt[e]; seg = g_off[e];
        bm = blockIdx.y * 128;
        if (bm >= cnt) return;
    } else {
        bm = blockIdx.y * 128;
    }
    bn = blockIdx.x * 128;

    const uint32_t sbase = smem_u32(sm);
    const uint32_t tbase = (sbase + 1023) & ~1023u;
    char* tp = (char*)sm + (tbase - sbase);

    // ---- global source mapping: 2 threads/row, 16 elems each ----
    const int arow = tid >> 1;
    const int half = tid & 1;
    int grow = bm + arow;
    size_t aoff;
    if (EXPERT) {
        int cl = (grow < cnt) ? grow : (cnt - 1);
        aoff = (size_t)(GATHER ? g_tok[seg + cl] : (seg + cl)) * K;
    } else {
        aoff = (size_t)grow * K;
    }
    const __nv_bfloat16* pAh = Ahi + aoff + half * 16;
    const __nv_bfloat16* pAl = Alo + aoff + half * 16;

    const int rB = bn + arow;
    const __nv_bfloat16* pBh = nullptr;
    const __nv_bfloat16* pBl = nullptr;
    const float* pBf = nullptr;
    if (CONVB) {
        if (SILU) {
            const float* src = (rB & 1) ? Bf1 : Bf0;
            pBf = src + ((size_t)e * HIDh + (rB >> 1)) * (size_t)K + half * 16;
        } else {
            pBf = Bf0 + ((size_t)(EXPERT ? e : 0) * N + rB) * (size_t)K + half * 16;
        }
    } else {
        const size_t boff = (EXPERT ? (size_t)e * N * K : 0) + (size_t)rB * K + half * 16;
        pBh = Bhi + boff;
        pBl = Blo + boff;
    }

    const uint32_t d0 = swz128((uint32_t)arow * 128 + half * 32);
    const uint32_t d1 = swz128((uint32_t)arow * 128 + half * 32 + 16);
    const uint32_t d2 = swz128((uint32_t)arow * 128 + 64 + half * 32);
    const uint32_t d3 = swz128((uint32_t)arow * 128 + 64 + half * 32 + 16);

    auto issueA = [&](int buf, int t) {
        const uint32_t aB = tbase + buf * STAGE_B;
        const int k0 = t * 32;
        cpa16(aB + d0, pAh + k0);
        cpa16(aB + d1, pAh + k0 + 8);
        cpa16(aB + d2, pAl + k0);
        cpa16(aB + d3, pAl + k0 + 8);
        if (!CONVB) {
            const uint32_t bB = aB + 16384;
            cpa16(bB + d0, pBh + k0);
            cpa16(bB + d1, pBh + k0 + 8);
            cpa16(bB + d2, pBl + k0);
            cpa16(bB + d3, pBl + k0 + 8);
        }
        asm volatile("cp.async.commit_group;" ::: "memory");
    };
    auto ldgB = [&](float4* b4, int t) {
        const float* p = pBf + t * 32;
        #pragma unroll
        for (int i = 0; i < 4; i++) b4[i] = *(const float4*)(p + i * 4);
    };
    auto stsB = [&](int buf, const float4* b4) {
        char* bB = tp + buf * STAGE_B + 16384;
        uint32_t hw[8], lw[8];
        #pragma unroll
        for (int i = 0; i < 4; i++) {
            const float* f = (const float*)&b4[i];
            #pragma unroll
            for (int j = 0; j < 2; j++) {
                __nv_bfloat16 h0, l0, h1, l1;
                split2(f[2 * j], h0, l0);
                split2(f[2 * j + 1], h1, l1);
                hw[i * 2 + j] = (uint32_t)(*(uint16_t*)&h0) | ((uint32_t)(*(uint16_t*)&h1) << 16);
                lw[i * 2 + j] = (uint32_t)(*(uint16_t*)&l0) | ((uint32_t)(*(uint16_t*)&l1) << 16);
            }
        }
        *(uint4*)(bB + d0) = make_uint4(hw[0], hw[1], hw[2], hw[3]);
        *(uint4*)(bB + d1) = make_uint4(hw[4], hw[5], hw[6], hw[7]);
        *(uint4*)(bB + d2) = make_uint4(lw[0], lw[1], lw[2], lw[3]);
        *(uint4*)(bB + d3) = make_uint4(lw[4], lw[5], lw[6], lw[7]);
    };

    // ---- warp tiling: 8 warps = 2(m) x 4(n), each 64x32 ----
    const int wid = tid >> 5, lane = tid & 31;
    const int wm = wid >> 2, wn = wid & 3;
    const int lrow = lane & 15;
    const int lcolb = (lane >> 4) * 16;

    float acc[4][4][4];
    #pragma unroll
    for (int i = 0; i < 4; i++)
        #pragma unroll
        for (int j = 0; j < 4; j++)
            #pragma unroll
            for (int q = 0; q < 4; q++) acc[i][j][q] = 0.f;

    const int NT = K >> 5;
    float4 bregs[4];

    issueA(0, 0);
    issueA(1, 1);
    if (CONVB) {
        ldgB(bregs, 0); stsB(0, bregs);
        ldgB(bregs, 1); stsB(1, bregs);
    }
    int buf = 0;
    for (int t = 0; t < NT; ++t) {
        if (t + 2 < NT) {
            asm volatile("cp.async.wait_group 1;" ::: "memory");
        } else {
            asm volatile("cp.async.wait_group 0;" ::: "memory");
        }
        __syncthreads();
        int nb = buf + 2; if (nb >= 3) nb -= 3;
        const bool more = (t + 2 < NT);
        if (more) {
            issueA(nb, t + 2);
            if (CONVB) ldgB(bregs, t + 2);
        }

        const uint32_t aB = tbase + buf * STAGE_B;
        const uint32_t bB = aB + 16384;
        #pragma unroll
        for (int s = 0; s < 2; s++) {
            uint32_t bh[2][4], bl[2][4];
            #pragma unroll
            for (int p = 0; p < 2; p++) {
                uint32_t ro = (uint32_t)(wn * 32 + p * 16 + lrow) * 128 + s * 32 + lcolb;
                ldsm_x4(bh[p], bB + swz128(ro));
                ldsm_x4(bl[p], bB + swz128(ro + 64));
            }
            #pragma unroll
            for (int i = 0; i < 4; i++) {
                uint32_t ah[4], al[4];
                uint32_t ro = (uint32_t)(wm * 64 + i * 16 + lrow) * 128 + s * 32 + lcolb;
                ldsm_x4(ah, aB + swz128(ro));
                ldsm_x4(al, aB + swz128(ro + 64));
                #pragma unroll
                for (int j = 0; j < 4; j++) {
                    const int p = j >> 1, o = j & 1;
                    mma_bf16(acc[i][j], ah, bh[p][o], bh[p][o + 2]);
                    mma_bf16(acc[i][j], ah, bl[p][o], bl[p][o + 2]);
                    mma_bf16(acc[i][j], al, bh[p][o], bh[p][o + 2]);
                }
            }
        }
        if (CONVB && more) stsB(nb, bregs);
        if (++buf == 3) buf = 0;
    }

    // ---- epilogue ----
    const int qr = lane >> 2;
    const int qc = (lane & 3) * 2;
    #pragma unroll
    for (int i = 0; i < 4; i++) {
        const int lm0 = wm * 64 + i * 16 + qr;
        #pragma unroll
        for (int j = 0; j < 4; j++) {
            const int c = bn + wn * 32 + j * 8 + qc;
            if (SILU) {
                const int h = c >> 1;
                float g0 = acc[i][j][0], u0 = acc[i][j][1];
                float g1 = acc[i][j][2], u1 = acc[i][j][3];
                float s0 = g0 / (1.f + __expf(-g0)) * u0;
                float s1 = g1 / (1.f + __expf(-g1)) * u1;
                if (bm + lm0 < cnt) {
                    __nv_bfloat16 hh, ll;
                    split2(s0, hh, ll);
                    size_t o = (size_t)(seg + bm + lm0) * HIDh + h;
                    g_hgb[o] = hh; g_lgb[o] = ll;
                }
                if (bm + lm0 + 8 < cnt) {
                    __nv_bfloat16 hh, ll;
                    split2(s1, hh, ll);
                    size_t o = (size_t)(seg + bm + lm0 + 8) * HIDh + h;
                    g_hgb[o] = hh; g_lgb[o] = ll;
                }
            } else {
                float2 v0 = make_float2(acc[i][j][0], acc[i][j][1]);
                float2 v1 = make_float2(acc[i][j][2], acc[i][j][3]);
                if (bias) {
                    float2 bv = *(const float2*)(bias + c);
                    v0.x += bv.x; v0.y += bv.y;
                    v1.x += bv.x; v1.y += bv.y;
                }
                if (ROPE) {
                    if (c < 2 * Dd) {     // q and k regions only
                        const int hh = (c >> 7) & (Hh - 1);
                        const int p = (c & 127) >> 1;
                        float ang = (float)hh * expf(-(float)p * (9.210340371976184f / 64.f));
                        float cs = cosf(ang), sn = sinf(ang);
                        float r0x = v0.x * cs - v0.y * sn;
                        float r0y = v0.x * sn + v0.y * cs;
                        v0.x = r0x; v0.y = r0y;
                        float r1x = v1.x * cs - v1.y * sn;
                        float r1y = v1.x * sn + v1.y * cs;
                        v1.x = r1x; v1.y = r1y;
                    }
                }
                if (EXPERT) {
                    if (bm + lm0 < cnt)
                        *(float2*)(C + (size_t)(seg + bm + lm0) * N + c) = v0;
                    if (bm + lm0 + 8 < cnt)
                        *(float2*)(C + (size_t)(seg + bm + lm0 + 8) * N + c) = v1;
                } else {
                    const int r0 = bm + lm0;
                    if (resid) {
                        float2 rv0 = *(const float2*)(resid + (size_t)r0 * Dd + c);
                        float2 rv1 = *(const float2*)(resid + (size_t)(r0 + 8) * Dd + c);
                        v0.x += rv0.x; v0.y += rv0.y;
                        v1.x += rv1.x; v1.y += rv1.y;
                    }
                    *(float2*)(C + (size_t)r0 * N + c)       = v0;
                    *(float2*)(C + (size_t)(r0 + 8) * N + c) = v1;
                }
            }
        }
    }
}

// ---------------- rmsnorm (optional fp32 + hi/lo plane outputs) ----------------
__global__ void rmsnorm_kernel(const float* __restrict__ x,
                               const float* __restrict__ w,
                               float* __restrict__ out_f32,
                               __nv_bfloat16* __restrict__ oh,
                               __nv_bfloat16* __restrict__ ol) {
    int t = blockIdx.x;
    const float* xr = x + (size_t)t * Dd;
    float ss = 0.f;
    for (int i = threadIdx.x; i < Dd; i += 256) { float vv = xr[i]; ss += vv * vv; }
    __shared__ float red[8];
    #pragma unroll
    for (int o = 16; o; o >>= 1) ss += __shfl_xor_sync(0xffffffffu, ss, o);
    if ((threadIdx.x & 31) == 0) red[threadIdx.x >> 5] = ss;
    __syncthreads();
    if (threadIdx.x < 8) {
        float v = red[threadIdx.x];
        #pragma unroll
        for (int o = 4; o; o >>= 1) v += __shfl_xor_sync(0xffu, v, o);
        if (threadIdx.x == 0) red[0] = v;
    }
    __syncthreads();
    float inv = 1.f / sqrtf(red[0] / (float)Dd + 1e-8f);
    for (int i = threadIdx.x; i < Dd; i += 256) {
        float v = xr[i] * inv * w[i];
        if (out_f32) out_f32[(size_t)t * Dd + i] = v;
        __nv_bfloat16 h, l;
        split2(v, h, l);
        oh[(size_t)t * Dd + i] = h;
        ol[(size_t)t * Dd + i] = l;
    }
}

// ---------------- attention: 64 q/block, 8 q/warp, lane-per-key, smem-w broadcast ----------------
// dyn smem floats: Qs[64][128] | Ks[32][132] | Vs[32][132] | Ws[8][32][8]
#define AQS 0
#define AKS 8192
#define AVS (8192 + 32 * 132)
#define AWS (8192 + 2 * 32 * 132)
#define ATT_SMEM ((8192 + 2 * 32 * 132 + 8 * 32 * 8) * 4)

__global__ __launch_bounds__(256)
void attn_kernel(const float* __restrict__ QKV,
                 __nv_bfloat16* __restrict__ Oh, __nv_bfloat16* __restrict__ Ol) {
    extern __shared__ float smf[];
    const int b = blockIdx.z, h = blockIdx.y, qg = blockIdx.x;
    const int tid = threadIdx.x;
    const int warp = tid >> 5, lane = tid & 31;

    // load Q block (64 rows x 128)
    for (int c = tid; c < 2048; c += 256) {
        int rr = c >> 5, c4 = (c & 31) * 4;
        *(float4*)&smf[AQS + rr * 128 + c4] =
            *(const float4*)&QKV[((size_t)(b * Ss + qg * 64 + rr)) * QKVN + h * DHh + c4];
    }

    const int q0 = qg * 64 + warp * 8;
    float m[8], l[8];
    float4 o[8];
    #pragma unroll
    for (int q = 0; q < 8; q++) {
        m[q] = -INFINITY; l[q] = 0.f;
        o[q] = make_float4(0.f, 0.f, 0.f, 0.f);
    }

    const int ntiles = 2 * qg + 2;
    for (int kt = 0; kt < ntiles; kt++) {
        __syncthreads();
        for (int c = tid; c < 1024; c += 256) {
            int rr = c >> 5, c4 = (c & 31) * 4;
            size_t g = ((size_t)(b * Ss + kt * 32 + rr)) * QKVN + h * DHh + c4;
            *(float4*)&smf[AKS + rr * 132 + c4] = *(const float4*)&QKV[g + Dd];
            *(float4*)&smf[AVS + rr * 132 + c4] = *(const float4*)&QKV[g + 2 * Dd];
        }
        __syncthreads();

        const int kj = kt * 32 + lane;
        float4 s4[8];
        #pragma unroll
        for (int q = 0; q < 8; q++) s4[q] = make_float4(0.f, 0.f, 0.f, 0.f);
        const float* krow = &smf[AKS + lane * 132];
        #pragma unroll 4
        for (int c4 = 0; c4 < 32; c4++) {
            float4 kv = *(const float4*)&krow[c4 * 4];
            #pragma unroll
            for (int q = 0; q < 8; q++) {
                float4 qv = *(const float4*)&smf[AQS + (warp * 8 + q) * 128 + c4 * 4];
                s4[q].x = fmaf(qv.x, kv.x, s4[q].x);
                s4[q].y = fmaf(qv.y, kv.y, s4[q].y);
                s4[q].z = fmaf(qv.z, kv.z, s4[q].z);
                s4[q].w = fmaf(qv.w, kv.w, s4[q].w);
            }
        }
        float s[8], w[8];
        #pragma unroll
        for (int q = 0; q < 8; q++) {
            float v = (s4[q].x + s4[q].y) + (s4[q].z + s4[q].w);
            s[q] = (kj <= q0 + q) ? v * 0.08838834764831845f : -INFINITY;
        }
        float tm[8];
        #pragma unroll
        for (int q = 0; q < 8; q++) tm[q] = s[q];
        #pragma unroll
        for (int ofs = 16; ofs; ofs >>= 1)
            #pragma unroll
            for (int q = 0; q < 8; q++)
                tm[q] = fmaxf(tm[q], __shfl_xor_sync(0xffffffffu, tm[q], ofs));
        float ts[8];
        #pragma unroll
        for (int q = 0; q < 8; q++) {
            float mnew = fmaxf(m[q], tm[q]);
            float corr = __expf(m[q] - mnew);
            w[q] = __expf(s[q] - mnew);
            m[q] = mnew;
            l[q] *= corr;
            o[q].x *= corr; o[q].y *= corr; o[q].z *= corr; o[q].w *= corr;
            ts[q] = w[q];
        }
        #pragma unroll
        for (int ofs = 16; ofs; ofs >>= 1)
            #pragma unroll
            for (int q = 0; q < 8; q++)
                ts[q] += __shfl_xor_sync(0xffffffffu, ts[q], ofs);
        #pragma unroll
        for (int q = 0; q < 8; q++) l[q] += ts[q];

        // stage w to per-warp smem so V-loop uses broadcast LDS instead of SHFL
        *(float4*)&smf[AWS + warp * 256 + lane * 8]     = make_float4(w[0], w[1], w[2], w[3]);
        *(float4*)&smf[AWS + warp * 256 + lane * 8 + 4] = make_float4(w[4], w[5], w[6], w[7]);
        __syncwarp();

        const float* vcol = &smf[AVS + lane * 4];
        const float* wrow = &smf[AWS + warp * 256];
        #pragma unroll 4
        for (int j = 0; j < 32; j++) {
            float4 wa = *(const float4*)&wrow[j * 8];
            float4 wb = *(const float4*)&wrow[j * 8 + 4];
            float4 vv = *(const float4*)&vcol[j * 132];
            o[0].x = fmaf(wa.x, vv.x, o[0].x); o[0].y = fmaf(wa.x, vv.y, o[0].y);
            o[0].z = fmaf(wa.x, vv.z, o[0].z); o[0].w = fmaf(wa.x, vv.w, o[0].w);
            o[1].x = fmaf(wa.y, vv.x, o[1].x); o[1].y = fmaf(wa.y, vv.y, o[1].y);
            o[1].z = fmaf(wa.y, vv.z, o[1].z); o[1].w = fmaf(wa.y, vv.w, o[1].w);
            o[2].x = fmaf(wa.z, vv.x, o[2].x); o[2].y = fmaf(wa.z, vv.y, o[2].y);
            o[2].z = fmaf(wa.z, vv.z, o[2].z); o[2].w = fmaf(wa.z, vv.w, o[2].w);
            o[3].x = fmaf(wa.w, vv.x, o[3].x); o[3].y = fmaf(wa.w, vv.y, o[3].y);
            o[3].z = fmaf(wa.w, vv.z, o[3].z); o[3].w = fmaf(wa.w, vv.w, o[3].w);
            o[4].x = fmaf(wb.x, vv.x, o[4].x); o[4].y = fmaf(wb.x, vv.y, o[4].y);
            o[4].z = fmaf(wb.x, vv.z, o[4].z); o[4].w = fmaf(wb.x, vv.w, o[4].w);
            o[5].x = fmaf(wb.y, vv.x, o[5].x); o[5].y = fmaf(wb.y, vv.y, o[5].y);
            o[5].z = fmaf(wb.y, vv.z, o[5].z); o[5].w = fmaf(wb.y, vv.w, o[5].w);
            o[6].x = fmaf(wb.z, vv.x, o[6].x); o[6].y = fmaf(wb.z, vv.y, o[6].y);
            o[6].z = fmaf(wb.z, vv.z, o[6].z); o[6].w = fmaf(wb.z, vv.w, o[6].w);
            o[7].x = fmaf(wb.w, vv.x, o[7].x); o[7].y = fmaf(wb.w, vv.y, o[7].y);
            o[7].z = fmaf(wb.w, vv.z, o[7].z); o[7].w = fmaf(wb.w, vv.w, o[7].w);
        }
    }

    #pragma unroll
    for (int q = 0; q < 8; q++) {
        float inv = 1.f / l[q];
        float4 f = make_float4(o[q].x * inv, o[q].y * inv, o[q].z * inv, o[q].w * inv);
        size_t base = ((size_t)(b * Ss + q0 + q)) * Dd + h * DHh + lane * 4;
        store_split4(Oh, Ol, base, f);
    }
}

// ---------------- router ----------------
__global__ void router_kernel(const float* __restrict__ xn, const float* __restrict__ wr,
                              const float* __restrict__ br) {
    int t = blockIdx.x;
    int warp = threadIdx.x >> 5, lane = threadIdx.x & 31;
    const float* xr = xn + (size_t)t * Dd;
    const float* w = wr + (size_t)warp * Dd;
    float s = 0.f;
    for (int i = lane; i < Dd; i += 32) s += xr[i] * w[i];
    #pragma unroll
    for (int o = 16; o; o >>= 1) s += __shfl_xor_sync(0xffffffffu, s, o);
    __shared__ float lg[Ee];
    if (lane == 0) lg[warp] = s + br[warp];
    __syncthreads();
    if (threadIdx.x == 0) {
        int i0 = 0; float v0 = lg[0];
        for (int e = 1; e < Ee; e++) if (lg[e] > v0) { v0 = lg[e]; i0 = e; }
        int i1 = -1; float v1 = -INFINITY;
        for (int e = 0; e < Ee; e++) if (e != i0 && lg[e] > v1) { v1 = lg[e]; i1 = e; }
        float e1 = expf(v1 - v0);
        float w0 = 1.f / (1.f + e1);
        g_tid2[t * 2] = i0; g_tid2[t * 2 + 1] = i1;
        g_twt[t * 2] = w0;  g_twt[t * 2 + 1] = e1 * w0;
    }
}

// ---------------- expert grouping ----------------
__global__ void build_lists_kernel() {
    __shared__ int cnt[Ee], run[Ee];
    int tid = threadIdx.x;
    if (tid < Ee) cnt[tid] = 0;
    __syncthreads();
    for (int i = tid; i < NPAIR; i += 256) atomicAdd(&cnt[g_tid2[i]], 1);
    __syncthreads();
    if (tid == 0) {
        int acc = 0;
        for (int e = 0; e < Ee; e++) { g_cnt[e] = cnt[e]; g_off[e] = acc; run[e] = acc; acc += cnt[e]; }
    }
    __syncthreads();
    for (int i = tid; i < NPAIR; i += 256) {
        int e = g_tid2[i];
        int pos = atomicAdd(&run[e], 1);
        g_tok[pos] = i >> 1;
        g_prow[i] = pos;
    }
}

// ---------------- combine ----------------
__global__ void combine_kernel(float* __restrict__ out) {
    int t = blockIdx.x;
    int r0 = g_prow[t * 2], r1 = g_prow[t * 2 + 1];
    float w0 = g_twt[t * 2], w1 = g_twt[t * 2 + 1];
    const float* e0 = g_eo + (size_t)r0 * Dd;
    const float* e1 = g_eo + (size_t)r1 * Dd;
    const float* xr = g_x2 + (size_t)t * Dd;
    float* orow = out + (size_t)t * Dd;
    for (int i = threadIdx.x; i < Dd; i += 256)
        orow[i] = xr[i] + w0 * e0[i] + w1 * e1[i];
}

// ---------------- host launcher ----------------
extern "C" void kernel_launch(void* const* d_in, const int* in_sizes, int n_in,
                              void* d_out, int out_size) {
    const float* x   = (const float*)d_in[0];
    const float* wq  = (const float*)d_in[1];
    const float* bq  = (const float*)d_in[2];
    const float* wk  = (const float*)d_in[3];
    const float* bk  = (const float*)d_in[4];
    const float* wv  = (const float*)d_in[5];
    const float* bv  = (const float*)d_in[6];
    const float* wo  = (const float*)d_in[7];
    const float* bo  = (const float*)d_in[8];
    const float* wr  = (const float*)d_in[9];
    const float* br  = (const float*)d_in[10];
    const float* wg  = (const float*)d_in[11];
    const float* wu  = (const float*)d_in[12];
    const float* wd  = (const float*)d_in[13];
    const float* r1w = (const float*)d_in[14];
    const float* r2w = (const float*)d_in[15];
    float* out = (float*)d_out;

    float *qkv, *x2, *xn2, *eo, *bqkv;
    __nv_bfloat16 *hxn1, *lxn1, *hatt, *latt, *hxn2, *lxn2, *hgb, *lgb;
    __nv_bfloat16 *hwqkv, *lwqkv, *hwo, *lwo;
    cudaGetSymbolAddress((void**)&qkv,  g_qkv);
    cudaGetSymbolAddress((void**)&x2,   g_x2);
    cudaGetSymbolAddress((void**)&xn2,  g_xn2);
    cudaGetSymbolAddress((void**)&eo,   g_eo);
    cudaGetSymbolAddress((void**)&bqkv, g_bqkv);
    cudaGetSymbolAddress((void**)&hxn1, g_hxn1);   cudaGetSymbolAddress((void**)&lxn1, g_lxn1);
    cudaGetSymbolAddress((void**)&hatt, g_hatt);   cudaGetSymbolAddress((void**)&latt, g_latt);
    cudaGetSymbolAddress((void**)&hxn2, g_hxn2);   cudaGetSymbolAddress((void**)&lxn2, g_lxn2);
    cudaGetSymbolAddress((void**)&hgb,  g_hgb);    cudaGetSymbolAddress((void**)&lgb,  g_lgb);
    cudaGetSymbolAddress((void**)&hwqkv, g_hwqkv); cudaGetSymbolAddress((void**)&lwqkv, g_lwqkv);
    cudaGetSymbolAddress((void**)&hwo,  g_hwo);    cudaGetSymbolAddress((void**)&lwo,  g_lwo);

    cudaFuncSetAttribute((const void*)tc_gemm<false, false, false, false, true>,
                         cudaFuncAttributeMaxDynamicSharedMemorySize, TC_SMEM);
    cudaFuncSetAttribute((const void*)tc_gemm<false, false, false, false, false>,
                         cudaFuncAttributeMaxDynamicSharedMemorySize, TC_SMEM);
    cudaFuncSetAttribute((const void*)tc_gemm<true, true, true, true, false>,
                         cudaFuncAttributeMaxDynamicSharedMemorySize, TC_SMEM);
    cudaFuncSetAttribute((const void*)tc_gemm<true, false, false, true, false>,
                         cudaFuncAttributeMaxDynamicSharedMemorySize, TC_SMEM);
    cudaFuncSetAttribute((const void*)attn_kernel,
                         cudaFuncAttributeMaxDynamicSharedMemorySize, ATT_SMEM);

    // 0) pack dense weights (small); MoE weights are converted in-GEMM
    const size_t qD = (size_t)Dd * Dd / 16;
    pack_kernel<<<Dd * Dd / 4096, 256>>>(wq, hwqkv, lwqkv, qD);
    pack_kernel<<<Dd * Dd / 4096, 256>>>(wk, hwqkv + (size_t)Dd * Dd, lwqkv + (size_t)Dd * Dd, qD);
    pack_kernel<<<Dd * Dd / 4096, 256>>>(wv, hwqkv + (size_t)2 * Dd * Dd, lwqkv + (size_t)2 * Dd * Dd, qD);
    pack_kernel<<<Dd * Dd / 4096, 256>>>(wo, hwo, lwo, qD);
    bias_cat_kernel<<<QKVN / 256, 256>>>(bq, bk, bv);

    // 1) rmsnorm1 -> planes only
    rmsnorm_kernel<<<Tt, 256>>>(x, r1w, nullptr, hxn1, lxn1);
    // 2) fused QKV projection with RoPE epilogue (N = 6144)
    tc_gemm<false, false, false, false, true><<<dim3(QKVN / 128, Tt / 128), 256, TC_SMEM>>>(
        hxn1, lxn1, hwqkv, lwqkv, nullptr, nullptr, qkv, bqkv, nullptr, QKVN, Dd);
    // 3) attention -> att planes
    attn_kernel<<<dim3(Ss / 64, Hh, Bb), 256, ATT_SMEM>>>(qkv, hatt, latt);
    // 4) output projection + residual
    tc_gemm<false, false, false, false, false><<<dim3(Dd / 128, Tt / 128), 256, TC_SMEM>>>(
        hatt, latt, hwo, lwo, nullptr, nullptr, x2, bo, x, Dd, Dd);
    // 5) rmsnorm2 -> fp32 (router) + planes (MoE)
    rmsnorm_kernel<<<Tt, 256>>>(x2, r2w, xn2, hxn2, lxn2);
    // 6) router + grouping
    router_kernel<<<Tt, 256>>>(xn2, wr, br);
    build_lists_kernel<<<1, 256>>>();
    // 7) MoE: fused gate+up (interleaved, silu epilogue, fp32 B in-GEMM), then down (fp32 B)
    tc_gemm<true, true, true, true, false><<<dim3(GUN / 128, NPAIR / 128, Ee), 256, TC_SMEM>>>(
        hxn2, lxn2, nullptr, nullptr, wg, wu, nullptr, nullptr, nullptr, GUN, Dd);
    tc_gemm<true, false, false, true, false><<<dim3(Dd / 128, NPAIR / 128, Ee), 256, TC_SMEM>>>(
        hgb, lgb, nullptr, nullptr, wd, nullptr, eo, nullptr, nullptr, Dd, HIDh);
    // 8) combine
    combine_kernel<<<Tt, 256>>>(out);
}